// round 7
// baseline (speedup 1.0000x reference)
#include <cuda_runtime.h>
#include <cuda_bf16.h>
#include <math.h>
#include <stdint.h>

#define LNUM   12
#define CDIM   768
#define HNUM   12
#define DHEAD  64
#define RF     64
#define NTOK   197
#define BATCH  32
#define TTOT   (BATCH*NTOK)     // 6304
#define NPATCH 196
#define PTOT   (BATCH*NPATCH)   // 6272
#define HIDD   3072
#define NCLS_  1000
#define QKVC   (3*CDIM)         // 2304

// weight split buffer offsets (elements)
#define WOFF_PATCH 0
#define WOFF_QKV   589824
#define WOFF_PROJ  21823488
#define WOFF_FC1   28901376
#define WOFF_FC2   57212928
#define WOFF_HEAD  85524480
#define WTOT       86292480

// ---------------- scratch (device globals; no allocs allowed) ----------------
__device__ float g_patch[PTOT*CDIM];
__device__ float g_t    [TTOT*CDIM];
__device__ float g_qkv  [TTOT*QKVC];
__device__ float g_qp   [TTOT*CDIM];
__device__ float g_kp   [TTOT*CDIM];
__device__ float g_kv   [BATCH*HNUM*RF*DHEAD];
__device__ float g_ks   [BATCH*HNUM*RF];
__device__ int   g_stab;
__device__ __nv_bfloat16 g_wh[WTOT];
__device__ __nv_bfloat16 g_wl[WTOT];
// split activations (GEMM A operands)
__device__ __nv_bfloat16 g_colh[PTOT*CDIM],  g_coll[PTOT*CDIM];
__device__ __nv_bfloat16 g_lnh [TTOT*CDIM],  g_lnl [TTOT*CDIM];
__device__ __nv_bfloat16 g_attnh[TTOT*CDIM], g_attnl[TTOT*CDIM];
__device__ __nv_bfloat16 g_hidh[TTOT*HIDD],  g_hidl[TTOT*HIDD];

__device__ __forceinline__ int   encf(float f){ int i=__float_as_int(f); return i<0 ? (i^0x7FFFFFFF) : i; }
__device__ __forceinline__ float decf(int i){ return __int_as_float(i<0 ? (i^0x7FFFFFFF) : i); }

__device__ __forceinline__ void split1(float v, __nv_bfloat16& h, __nv_bfloat16& l){
    h = __float2bfloat16(v);
    l = __float2bfloat16(v - __bfloat162float(h));
}

// ---------------- weight split ----------------
__global__ void wsplit4_k(const float* __restrict__ w,
                          __nv_bfloat16* __restrict__ hi,
                          __nv_bfloat16* __restrict__ lo, int n4){
    int i = blockIdx.x*blockDim.x + threadIdx.x;
    if (i >= n4) return;
    float4 v = ((const float4*)w)[i];
    __nv_bfloat16 hx,lx,hy,ly,hz,lz,hw,lw;
    split1(v.x,hx,lx); split1(v.y,hy,ly); split1(v.z,hz,lz); split1(v.w,hw,lw);
    __nv_bfloat162* h2 = (__nv_bfloat162*)hi;
    __nv_bfloat162* l2 = (__nv_bfloat162*)lo;
    h2[i*2]   = __halves2bfloat162(hx, hy);
    h2[i*2+1] = __halves2bfloat162(hz, hw);
    l2[i*2]   = __halves2bfloat162(lx, ly);
    l2[i*2+1] = __halves2bfloat162(lz, lw);
}

// ---------------- im2col (writes split bf16 directly) ----------------
__global__ void im2col_k(const float* __restrict__ x){
    int idx = blockIdx.x*blockDim.x + threadIdx.x;
    if (idx >= PTOT*CDIM) return;
    int p = idx / CDIM, j = idx % CDIM;
    int b = p / NPATCH, pin = p % NPATCH;
    int py = pin / 14, px = pin % 14;
    int ci = j >> 8, rem = j & 255;
    int ky = rem >> 4, kx = rem & 15;
    float v = x[((b*3 + ci)*224 + (py*16+ky))*224 + (px*16+kx)];
    __nv_bfloat16 h,l; split1(v,h,l);
    g_colh[idx] = h; g_coll[idx] = l;
}

// ---------------- assemble ----------------
__global__ void assemble_k(const float* __restrict__ cls, const float* __restrict__ pos){
    int idx = blockIdx.x*blockDim.x + threadIdx.x;
    if (idx >= TTOT*CDIM) return;
    int t = idx / CDIM, c = idx % CDIM;
    int b = t / NTOK, n = t % NTOK;
    float v = (n == 0) ? cls[c] : g_patch[(b*NPATCH + n - 1)*CDIM + c];
    g_t[idx] = v + pos[n*CDIM + c];
}

// ---------------- layernorm (writes split bf16) ----------------
__global__ void ln_k(const float* __restrict__ in, long istride,
                     const float* __restrict__ w, const float* __restrict__ bb,
                     __nv_bfloat16* __restrict__ oh, __nv_bfloat16* __restrict__ ol){
    long row = blockIdx.x;
    const float* xr = in + row*istride;
    long ro = row*(long)CDIM;
    int tid = threadIdx.x;
    float v0 = xr[tid], v1 = xr[tid+256], v2 = xr[tid+512];
    float s  = v0+v1+v2;
    float s2 = v0*v0 + v1*v1 + v2*v2;
    __shared__ float sh1[8], sh2[8], mv[2];
    #pragma unroll
    for (int o=16;o>0;o>>=1){
        s  += __shfl_down_sync(0xffffffffu, s,  o);
        s2 += __shfl_down_sync(0xffffffffu, s2, o);
    }
    if ((tid&31)==0){ sh1[tid>>5]=s; sh2[tid>>5]=s2; }
    __syncthreads();
    if (tid < 32){
        float a = (tid<8)? sh1[tid] : 0.f;
        float b2= (tid<8)? sh2[tid] : 0.f;
        #pragma unroll
        for (int o=4;o>0;o>>=1){
            a  += __shfl_down_sync(0xffffffffu, a,  o);
            b2 += __shfl_down_sync(0xffffffffu, b2, o);
        }
        if (tid==0){
            float mu = a * (1.f/CDIM);
            float var = b2 * (1.f/CDIM) - mu*mu;
            mv[0] = mu; mv[1] = rsqrtf(var + 1e-6f);
        }
    }
    __syncthreads();
    float mu = mv[0], rs = mv[1];
    __nv_bfloat16 h,l;
    float y0 = (v0-mu)*rs*w[tid]     + bb[tid];
    float y1 = (v1-mu)*rs*w[tid+256] + bb[tid+256];
    float y2 = (v2-mu)*rs*w[tid+512] + bb[tid+512];
    split1(y0,h,l); oh[ro+tid]     = h; ol[ro+tid]     = l;
    split1(y1,h,l); oh[ro+tid+256] = h; ol[ro+tid+256] = l;
    split1(y2,h,l); oh[ro+tid+512] = h; ol[ro+tid+512] = l;
}

// ---------------- performer feature maps ----------------
__global__ void phiq_k(const float* __restrict__ worf){
    int blk = blockIdx.x;
    int t = blk / HNUM, h = blk - t*HNUM;
    int m = threadIdx.x;
    __shared__ float dv[64];
    __shared__ float red[64];
    dv[m] = g_qkv[(long)t*QKVC + h*DHEAD + m];
    __syncthreads();
    red[m] = dv[m]; __syncthreads();
    #pragma unroll
    for (int o=32;o>0;o>>=1){ if (m<o) red[m]+=red[m+o]; __syncthreads(); }
    float diag = red[0] * 0.0625f;
    __syncthreads();
    float dot = 0.f;
    const float* wr = worf + m*DHEAD;
    #pragma unroll 16
    for (int d=0; d<DHEAD; d++) dot = fmaf(dv[d], wr[d], dot);
    red[m] = dot; __syncthreads();
    #pragma unroll
    for (int o=32;o>0;o>>=1){ if (m<o) red[m]=fmaxf(red[m],red[m+o]); __syncthreads(); }
    float stab = red[0];
    g_qp[(long)t*CDIM + h*DHEAD + m] = 0.35355339f*(expf(dot - diag - stab) + 1e-6f);
}

__global__ void reset_stab_k(){ g_stab = (int)0x80000000; }

__global__ void phik_k(const float* __restrict__ worf){
    int blk = blockIdx.x;
    int t = blk / HNUM, h = blk - t*HNUM;
    int m = threadIdx.x;
    __shared__ float dv[64];
    __shared__ float red[64];
    dv[m] = g_qkv[(long)t*QKVC + CDIM + h*DHEAD + m];
    __syncthreads();
    red[m] = dv[m]; __syncthreads();
    #pragma unroll
    for (int o=32;o>0;o>>=1){ if (m<o) red[m]+=red[m+o]; __syncthreads(); }
    float diag = red[0] * 0.0625f;
    __syncthreads();
    float dot = 0.f;
    const float* wr = worf + m*DHEAD;
    #pragma unroll 16
    for (int d=0; d<DHEAD; d++) dot = fmaf(dv[d], wr[d], dot);
    g_kp[(long)t*CDIM + h*DHEAD + m] = dot - diag;
    red[m] = dot; __syncthreads();
    #pragma unroll
    for (int o=32;o>0;o>>=1){ if (m<o) red[m]=fmaxf(red[m],red[m+o]); __syncthreads(); }
    if (m==0) atomicMax(&g_stab, encf(red[0]));
}

__global__ void kexp_k(){
    int idx = blockIdx.x*blockDim.x + threadIdx.x;
    if (idx >= TTOT*CDIM) return;
    float stab = decf(g_stab);
    g_kp[idx] = 0.35355339f*(expf(g_kp[idx] - stab) + 1e-6f);
}

// ---------------- kv / num ----------------
__global__ void __launch_bounds__(256) kv_k(){
    int bh = blockIdx.x;
    int b = bh / HNUM, h = bh - b*HNUM;
    __shared__ float kps[64], vs[64];
    int tid = threadIdx.x;
    int m = tid >> 2, d0 = (tid & 3) * 16;
    float acc[16];
    #pragma unroll
    for (int j=0;j<16;j++) acc[j]=0.f;
    float ksacc = 0.f;
    for (int l=0; l<NTOK; l++){
        long t = (long)b*NTOK + l;
        if (tid < 64)        kps[tid]    = g_kp [t*CDIM + h*DHEAD + tid];
        else if (tid < 128)  vs[tid-64]  = g_qkv[t*QKVC + 2*CDIM + h*DHEAD + (tid-64)];
        __syncthreads();
        float km = kps[m];
        #pragma unroll
        for (int j=0;j<16;j++) acc[j] = fmaf(km, vs[d0+j], acc[j]);
        if (tid < 64) ksacc += kps[tid];
        __syncthreads();
    }
    #pragma unroll
    for (int j=0;j<16;j++) g_kv[((long)bh*RF + m)*DHEAD + d0 + j] = acc[j];
    if (tid < 64) g_ks[bh*RF + tid] = ksacc;
}

__global__ void __launch_bounds__(256) num_k(){
    int bh = blockIdx.x;
    int b = bh / HNUM, h = bh - b*HNUM;
    __shared__ float kvs[64][65];
    __shared__ float kss[64];
    int tid = threadIdx.x;
    for (int e=tid; e<RF*DHEAD; e+=256){
        kvs[e>>6][e&63] = g_kv[(long)bh*RF*DHEAD + e];
    }
    if (tid < 64) kss[tid] = g_ks[bh*RF + tid];
    __syncthreads();
    int grp = tid >> 6, d = tid & 63;
    for (int l=grp; l<NTOK; l+=4){
        long t = (long)b*NTOK + l;
        const float* qrow = &g_qp[t*CDIM + h*DHEAD];
        float num=0.f, den=0.f;
        #pragma unroll 16
        for (int mm=0; mm<RF; mm++){
            float qv = __ldg(qrow + mm);
            num = fmaf(qv, kvs[mm][d], num);
            den = fmaf(qv, kss[mm], den);
        }
        float v = num/den;
        __nv_bfloat16 hh,ll; split1(v,hh,ll);
        long o = t*CDIM + h*DHEAD + d;
        g_attnh[o] = hh; g_attnl[o] = ll;
    }
}

// ---------------- bf16-split tensor-core NT GEMM (ldmatrix + cp.async) -------
// C = act((Ah+Al) @ (Wh+Wl)^T + bias); 3 MMA terms HH+HL+LH, fp32 accum.
// CTA tile 128x128, 4 warps (64x64 warp tile), K-chunk 32, 2-stage cp.async.
#define SROW 20           // u32 per smem row (16 data + 4 pad) = 80 bytes
#define TILE_U32 2560     // 128*SROW
#define STAGE_U32 10240   // 4 tiles (AH,AL,BH,BL)

__device__ __forceinline__ uint32_t smem_u32(const void* p){
    uint32_t a;
    asm("{ .reg .u64 t; cvta.to.shared.u64 t, %1; cvt.u32.u64 %0, t; }" : "=r"(a) : "l"(p));
    return a;
}
#define CP16(dst,src,sz) asm volatile("cp.async.cg.shared.global [%0],[%1],16,%2;" :: "r"(dst),"l"(src),"r"(sz))
#define CP_COMMIT()      asm volatile("cp.async.commit_group;" ::: "memory")
#define CP_WAIT0()       asm volatile("cp.async.wait_group 0;" ::: "memory")
#define CP_WAIT1()       asm volatile("cp.async.wait_group 1;" ::: "memory")

#define LDSM4(r, a) \
    asm volatile("ldmatrix.sync.aligned.m8n8.x4.shared.b16 {%0,%1,%2,%3}, [%4];" \
        : "=r"((r)[0]), "=r"((r)[1]), "=r"((r)[2]), "=r"((r)[3]) : "r"(a))

__device__ __forceinline__ void mma16(float* c, const uint32_t* a, const uint32_t* b){
    asm volatile("mma.sync.aligned.m16n8k16.row.col.f32.bf16.bf16.f32 "
        "{%0,%1,%2,%3}, {%4,%5,%6,%7}, {%8,%9}, {%0,%1,%2,%3};"
        : "+f"(c[0]), "+f"(c[1]), "+f"(c[2]), "+f"(c[3])
        : "r"(a[0]), "r"(a[1]), "r"(a[2]), "r"(a[3]), "r"(b[0]), "r"(b[1]));
}

// OMODE: 0 = f32 store, 1 = f32 store + residual, 2 = bf16 hi/lo split store
template<int ACT, int OMODE>
__global__ void __launch_bounds__(128,2) gemm_bf(
        const __nv_bfloat16* __restrict__ Ah,
        const __nv_bfloat16* __restrict__ Al, int lda,
        const __nv_bfloat16* __restrict__ Wh,
        const __nv_bfloat16* __restrict__ Wl, int ldw,
        const float* __restrict__ bias,
        float* __restrict__ Cd,
        __nv_bfloat16* __restrict__ Oh,
        __nv_bfloat16* __restrict__ Ol, int ldc,
        int Mrows, int Ncols, int K)
{
    extern __shared__ uint32_t sm[];
    uint32_t sb = smem_u32(sm);

    int tid  = threadIdx.x;
    int wid  = tid >> 5, lane = tid & 31;
    int wm   = (wid >> 1) * 64;       // warp row offset
    int wn   = (wid & 1)  * 64;       // warp col offset
    int row0 = blockIdx.y * 128;
    int col0 = blockIdx.x * 128;

    float acc[4][8][4];
    #pragma unroll
    for (int i=0;i<4;i++)
        #pragma unroll
        for (int j=0;j<8;j++)
            #pragma unroll
            for (int e=0;e<4;e++) acc[i][j][e]=0.f;

    // ---- cp.async staging geometry: 128 thr; per tile 4 rows/thread ----
    const int rr = tid >> 2, cc = tid & 3;   // rr 0..31, cc 16B chunk
    long aoff[4]; int sza[4]; uint32_t da[4];
    long boff[4]; int szb[4]; uint32_t db[4];
    #pragma unroll
    for (int j=0;j<4;j++){
        int r = rr + 32*j;
        int ra = row0 + r;
        sza[j] = (ra < Mrows) ? 16 : 0;
        aoff[j] = (long)min(ra, Mrows-1)*lda + cc*8;
        int rb = col0 + r;
        szb[j] = (rb < Ncols) ? 16 : 0;
        boff[j] = (long)min(rb, Ncols-1)*ldw + cc*8;
        da[j] = sb + (r*SROW + cc*4)*4;
        db[j] = da[j] + 2*TILE_U32*4;
    }

    // ---- ldmatrix lane addressing (byte offsets into a stage) ----
    const int mat = lane >> 3, rim = lane & 7;
    // A: mats {(m0,k0),(m8,k0),(m0,k8),(m8,k8)}
    uint32_t aA = sb + (uint32_t)(wm + rim + (mat & 1)*8)*80u + (uint32_t)(mat >> 1)*16u;
    // B: mats {(n0,k0),(n0,k8),(n8,k0),(n8,k8)}  -> regs {nt0 b0, nt0 b1, nt1 b0, nt1 b1}
    uint32_t aB = sb + 2*TILE_U32*4 + (uint32_t)(wn + rim + (mat >> 1)*8)*80u + (uint32_t)(mat & 1)*16u;

    const int nchunk = K >> 5;

    // prologue: chunk 0 into stage 0
    #pragma unroll
    for (int j=0;j<4;j++){
        CP16(da[j],              Ah + aoff[j], sza[j]);
        CP16(da[j] + TILE_U32*4, Al + aoff[j], sza[j]);
        CP16(db[j],              Wh + boff[j], szb[j]);
        CP16(db[j] + TILE_U32*4, Wl + boff[j], szb[j]);
    }
    CP_COMMIT();

    for (int c = 0; c < nchunk; c++){
        if (c + 1 < nchunk){
            long k8 = (long)(c+1) * 32;
            uint32_t so = ((c+1) & 1) * STAGE_U32 * 4;
            #pragma unroll
            for (int j=0;j<4;j++){
                CP16(da[j] + so,              Ah + aoff[j] + k8, sza[j]);
                CP16(da[j] + so + TILE_U32*4, Al + aoff[j] + k8, sza[j]);
                CP16(db[j] + so,              Wh + boff[j] + k8, szb[j]);
                CP16(db[j] + so + TILE_U32*4, Wl + boff[j] + k8, szb[j]);
            }
            CP_COMMIT();
            CP_WAIT1();
        } else {
            CP_WAIT0();
        }
        __syncthreads();

        uint32_t S = (c & 1) * STAGE_U32 * 4;

        #pragma unroll
        for (int ks = 0; ks < 2; ks++){
            uint32_t kb = S + ks*32;
            uint32_t bH[4][4], bL[4][4];
            #pragma unroll
            for (int p = 0; p < 4; p++){
                uint32_t ad = aB + kb + (uint32_t)p*16u*80u;
                LDSM4(bH[p], ad);
                LDSM4(bL[p], ad + TILE_U32*4);
            }
            #pragma unroll
            for (int mt = 0; mt < 4; mt++){
                uint32_t ad = aA + kb + (uint32_t)mt*16u*80u;
                uint32_t aHf[4], aLf[4];
                LDSM4(aHf, ad);
                LDSM4(aLf, ad + TILE_U32*4);
                #pragma unroll
                for (int nt = 0; nt < 8; nt++){
                    const uint32_t* bh = &bH[nt>>1][(nt&1)*2];
                    const uint32_t* bl = &bL[nt>>1][(nt&1)*2];
                    mma16(acc[mt][nt], aHf, bh);
                    mma16(acc[mt][nt], aHf, bl);
                    mma16(acc[mt][nt], aLf, bh);
                }
            }
        }
        __syncthreads();
    }

    // epilogue
    #pragma unroll
    for (int mt=0; mt<4; mt++){
        int r0 = row0 + wm + mt*16 + (lane >> 2);
        #pragma unroll
        for (int nt=0; nt<8; nt++){
            int c0 = col0 + wn + nt*8 + (lane & 3)*2;
            #pragma unroll
            for (int e=0; e<4; e++){
                int r = r0 + (e>>1)*8;
                int c = c0 + (e&1);
                if (r >= Mrows || c >= Ncols) continue;
                float v = acc[mt][nt][e] + bias[c];
                if (ACT == 1) v = v * normcdff(v);
                long o = (long)r*ldc + c;
                if (OMODE == 0) Cd[o] = v;
                else if (OMODE == 1) Cd[o] += v;
                else {
                    __nv_bfloat16 hh,ll; split1(v,hh,ll);
                    Oh[o] = hh; Ol[o] = ll;
                }
            }
        }
    }
}

// ---------------- driver ----------------
extern "C" void kernel_launch(void* const* d_in, const int* in_sizes, int n_in,
                              void* d_out, int out_size){
    (void)in_sizes; (void)n_in; (void)out_size;
    const float* x       = (const float*)d_in[0];
    const float* patch_w = (const float*)d_in[1];
    const float* patch_b = (const float*)d_in[2];
    const float* cls     = (const float*)d_in[3];
    const float* pos     = (const float*)d_in[4];
    const float* ln1w    = (const float*)d_in[5];
    const float* ln1b    = (const float*)d_in[6];
    const float* qkvw    = (const float*)d_in[7];
    const float* qkvb    = (const float*)d_in[8];
    const float* worf    = (const float*)d_in[9];
    const float* projw   = (const float*)d_in[10];
    const float* projb   = (const float*)d_in[11];
    const float* ln2w    = (const float*)d_in[12];
    const float* ln2b    = (const float*)d_in[13];
    const float* fc1w    = (const float*)d_in[14];
    const float* fc1b    = (const float*)d_in[15];
    const float* fc2w    = (const float*)d_in[16];
    const float* fc2b    = (const float*)d_in[17];
    const float* lnfw    = (const float*)d_in[18];
    const float* lnfb    = (const float*)d_in[19];
    const float* headw   = (const float*)d_in[20];
    const float* headb   = (const float*)d_in[21];
    float* out = (float*)d_out;

    float *patchp,*tp,*qkvp;
    __nv_bfloat16 *whp,*wlp,*colh,*coll,*lnh,*lnl,*ath,*atl,*hih,*hil;
    cudaGetSymbolAddress((void**)&patchp,g_patch);
    cudaGetSymbolAddress((void**)&tp,    g_t);
    cudaGetSymbolAddress((void**)&qkvp,  g_qkv);
    cudaGetSymbolAddress((void**)&whp,   g_wh);
    cudaGetSymbolAddress((void**)&wlp,   g_wl);
    cudaGetSymbolAddress((void**)&colh,  g_colh);
    cudaGetSymbolAddress((void**)&coll,  g_coll);
    cudaGetSymbolAddress((void**)&lnh,   g_lnh);
    cudaGetSymbolAddress((void**)&lnl,   g_lnl);
    cudaGetSymbolAddress((void**)&ath,   g_attnh);
    cudaGetSymbolAddress((void**)&atl,   g_attnl);
    cudaGetSymbolAddress((void**)&hih,   g_hidh);
    cudaGetSymbolAddress((void**)&hil,   g_hidl);

    const int SMB = STAGE_U32 * 2 * 4;   // 80KB
    cudaFuncSetAttribute(gemm_bf<0,0>, cudaFuncAttributeMaxDynamicSharedMemorySize, SMB);
    cudaFuncSetAttribute(gemm_bf<0,1>, cudaFuncAttributeMaxDynamicSharedMemorySize, SMB);
    cudaFuncSetAttribute(gemm_bf<1,2>, cudaFuncAttributeMaxDynamicSharedMemorySize, SMB);

    // ---- weight pre-split ----
    {
        auto ws = [&](const float* src, long off, long cnt){
            wsplit4_k<<<(int)((cnt/4 + 255)/256), 256>>>(src, whp+off, wlp+off, (int)(cnt/4));
        };
        ws(patch_w, WOFF_PATCH, 589824);
        ws(headw,   WOFF_HEAD,  768000);
        for (int i=0;i<LNUM;i++){
            ws(qkvw  + (long)i*QKVC*CDIM, WOFF_QKV  + (long)i*1769472, 1769472);
            ws(projw + (long)i*CDIM*CDIM, WOFF_PROJ + (long)i*589824,  589824);
            ws(fc1w  + (long)i*HIDD*CDIM, WOFF_FC1  + (long)i*2359296, 2359296);
            ws(fc2w  + (long)i*CDIM*HIDD, WOFF_FC2  + (long)i*2359296, 2359296);
        }
    }

    const int mtT = (TTOT + 127) / 128;   // 50
    const int mtP = (PTOT + 127) / 128;   // 49

    im2col_k<<<(PTOT*CDIM+255)/256, 256>>>(x);
    gemm_bf<0,0><<<dim3(CDIM/128, mtP), 128, SMB>>>(colh, coll, CDIM,
            whp+WOFF_PATCH, wlp+WOFF_PATCH, CDIM, patch_b,
            patchp, nullptr, nullptr, CDIM, PTOT, CDIM, CDIM);
    assemble_k<<<(TTOT*CDIM+255)/256, 256>>>(cls, pos);

    for (int i=0; i<LNUM; i++){
        ln_k<<<TTOT, 256>>>(tp, CDIM, ln1w + i*CDIM, ln1b + i*CDIM, lnh, lnl);
        gemm_bf<0,0><<<dim3(QKVC/128, mtT), 128, SMB>>>(lnh, lnl, CDIM,
                whp+WOFF_QKV+(long)i*1769472, wlp+WOFF_QKV+(long)i*1769472, CDIM,
                qkvb + i*QKVC, qkvp, nullptr, nullptr, QKVC, TTOT, QKVC, CDIM);
        phiq_k<<<TTOT*HNUM, 64>>>(worf + (long)i*RF*DHEAD);
        reset_stab_k<<<1,1>>>();
        phik_k<<<TTOT*HNUM, 64>>>(worf + (long)i*RF*DHEAD);
        kexp_k<<<(TTOT*CDIM+255)/256, 256>>>();
        kv_k<<<BATCH*HNUM, 256>>>();
        num_k<<<BATCH*HNUM, 256>>>();
        gemm_bf<0,1><<<dim3(CDIM/128, mtT), 128, SMB>>>(ath, atl, CDIM,
                whp+WOFF_PROJ+(long)i*589824, wlp+WOFF_PROJ+(long)i*589824, CDIM,
                projb + i*CDIM, tp, nullptr, nullptr, CDIM, TTOT, CDIM, CDIM);
        ln_k<<<TTOT, 256>>>(tp, CDIM, ln2w + i*CDIM, ln2b + i*CDIM, lnh, lnl);
        gemm_bf<1,2><<<dim3(HIDD/128, mtT), 128, SMB>>>(lnh, lnl, CDIM,
                whp+WOFF_FC1+(long)i*2359296, wlp+WOFF_FC1+(long)i*2359296, CDIM,
                fc1b + i*HIDD, nullptr, hih, hil, HIDD, TTOT, HIDD, CDIM);
        gemm_bf<0,1><<<dim3(CDIM/128, mtT), 128, SMB>>>(hih, hil, HIDD,
                whp+WOFF_FC2+(long)i*2359296, wlp+WOFF_FC2+(long)i*2359296, HIDD,
                fc2b + i*CDIM, tp, nullptr, nullptr, CDIM, TTOT, CDIM, HIDD);
    }

    ln_k<<<BATCH, 256>>>(tp, (long)NTOK*CDIM, lnfw, lnfb, lnh, lnl);
    gemm_bf<0,0><<<dim3((NCLS_+127)/128, 1), 128, SMB>>>(lnh, lnl, CDIM,
            whp+WOFF_HEAD, wlp+WOFF_HEAD, CDIM, headb,
            out, nullptr, nullptr, NCLS_, BATCH, NCLS_, CDIM);
}